// round 15
// baseline (speedup 1.0000x reference)
#include <cuda_runtime.h>
#include <cuda_bf16.h>
#include <mma.h>
#include <math.h>
#include <stdint.h>

using namespace nvcuda;

// Problem constants
#define N_TOK 16384
#define DIM   256
#define NEXP  8
#define HID   512
#define TOPK  2
#define NASSIGN (N_TOK * TOPK)            // 32768
#define NPAD (NASSIGN + NEXP * 128)       // 33792 padded positions
#define MAX_TILES (NPAD / 128)            // 264
#define T_TILES 89                        // grid for one third
#define HROWS (89 * 128)                  // 11392 per-third h rows

// GEMM tiling: CTA 128x128, K chunk 32, wmma s8 16x16x16, 16 warps (32x32 tiles)
#define KB   32
#define LDA  48        // A smem leading dim (int8): 32 + 16 pad (mult of 16)
#define LDB  144       // B smem leading dim (int8): 128 + 16 pad (mult of 16)
#define LDS_ 20        // stag leading dim (int32/fp32 words)

// ================= device scratch (~85 MB) =================
__device__ int   g_counts[NEXP];
__device__ int   g_cursor[NEXP];
__device__ int   g_off[NEXP + 1];
__device__ int   g_ntiles;
__device__ int   g_tile_e[MAX_TILES];
__device__ int   g_tile_base[MAX_TILES];
__device__ int   g_tile_rows[MAX_TILES];

__device__ int   g_topi[NASSIGN];
__device__ float g_topw[NASSIGN];
__device__ int   g_ptok[NPAD];
__device__ int   g_tok2pos[NASSIGN];

// int8 dual-plane operands + scales (inv = dequant multiplier)
__device__ signed char g_xq1[(size_t)N_TOK * DIM];
__device__ signed char g_xq2[(size_t)N_TOK * DIM];
__device__ float       g_xs[N_TOK];
__device__ signed char g_w1q1[(size_t)NEXP * DIM * HID];   // [E][D][H]
__device__ signed char g_w1q2[(size_t)NEXP * DIM * HID];
__device__ float       g_w1s[NEXP * HID];
__device__ signed char g_w2q1[(size_t)NEXP * HID * DIM];   // [E][H][D]
__device__ signed char g_w2q2[(size_t)NEXP * HID * DIM];
__device__ float       g_w2s[NEXP * DIM];

__device__ float       g_h[(size_t)HROWS * HID];           // raw fp32 GEMM1 out (per-third)
__device__ signed char g_hq1[(size_t)HROWS * HID];
__device__ signed char g_hq2[(size_t)HROWS * HID];
__device__ float       g_hs[HROWS];
__device__ float       g_y[(size_t)NPAD * DIM];

// ================= kernel 0: init =================
__global__ void init_kernel() {
    int t = threadIdx.x;
    if (t < NEXP) { g_counts[t] = 0; g_cursor[t] = 0; }
}

// ================= kernel 1: gate (top-2 + softmax) =================
__global__ void gate_kernel(const float* __restrict__ x,
                            const float* __restrict__ Wg) {
    __shared__ float sWg[NEXP][DIM];
    int tid = threadIdx.x;
    for (int i = tid; i < DIM * NEXP; i += blockDim.x) {
        int e = i & (NEXP - 1);
        int d = i >> 3;
        sWg[e][d] = Wg[i];
    }
    __syncthreads();

    int warp = tid >> 5, lane = tid & 31;
    int n = blockIdx.x * 4 + warp;
    if (n >= N_TOK) return;

    float lg[NEXP];
#pragma unroll
    for (int e = 0; e < NEXP; e++) lg[e] = 0.f;
#pragma unroll
    for (int j = 0; j < 8; j++) {
        int d = lane + 32 * j;
        float xv = x[(size_t)n * DIM + d];
#pragma unroll
        for (int e = 0; e < NEXP; e++) lg[e] += xv * sWg[e][d];
    }
#pragma unroll
    for (int e = 0; e < NEXP; e++)
#pragma unroll
        for (int o = 16; o > 0; o >>= 1)
            lg[e] += __shfl_xor_sync(0xffffffffu, lg[e], o);

    if (lane == 0) {
        float m1 = lg[0]; int i1 = 0;
#pragma unroll
        for (int e = 1; e < NEXP; e++) if (lg[e] > m1) { m1 = lg[e]; i1 = e; }
        float m2 = -1e30f; int i2 = 0;
#pragma unroll
        for (int e = 0; e < NEXP; e++)
            if (e != i1 && lg[e] > m2) { m2 = lg[e]; i2 = e; }
        float p2 = expf(m2 - m1);
        float inv = 1.f / (1.f + p2);
        g_topi[2 * n + 0] = i1;  g_topw[2 * n + 0] = inv;
        g_topi[2 * n + 1] = i2;  g_topw[2 * n + 1] = p2 * inv;
        atomicAdd(&g_counts[i1], 1);
        atomicAdd(&g_counts[i2], 1);
    }
}

// ================= kernel 2: prefix (128-aligned) + tile descriptors ========
__global__ void prep_kernel() {
    int off = 0;
    for (int e = 0; e < NEXP; e++) {
        g_off[e] = off;
        off += (g_counts[e] + 127) & ~127;
    }
    g_off[NEXP] = off;
    int t = 0;
    for (int e = 0; e < NEXP; e++) {
        int cnt = g_counts[e];
        for (int s = 0; s < cnt; s += 128) {
            g_tile_e[t] = e;
            g_tile_base[t] = g_off[e] + s;
            g_tile_rows[t] = min(128, cnt - s);
            t++;
        }
    }
    g_ntiles = t;
}

// ================= kernel 3: scatter =================
__global__ void scatter_kernel() {
    int idx = blockIdx.x * blockDim.x + threadIdx.x;
    if (idx >= NASSIGN) return;
    int e = g_topi[idx];
    int pos = g_off[e] + atomicAdd(&g_cursor[e], 1);
    g_ptok[pos] = idx >> 1;
    g_tok2pos[idx] = pos;
}

// ===== quantization helpers =====
__device__ __forceinline__ float warp_max(float m) {
#pragma unroll
    for (int o = 16; o > 0; o >>= 1)
        m = fmaxf(m, __shfl_xor_sync(0xffffffffu, m, o));
    return m;
}
__device__ __forceinline__ void quant2(float u, signed char& q1, signed char& q2) {
    float r1 = rintf(u);
    float r2 = rintf((u - r1) * 256.f);
    r2 = fminf(127.f, fmaxf(-127.f, r2));
    q1 = (signed char)(int)r1;
    q2 = (signed char)(int)r2;
}

// ================= conv kernels (globals referenced inside device code) ======
// x: one warp per token row (256 elems, 8 contiguous per lane)
__global__ void conv_x_kernel(const float* __restrict__ x) {
    int w = (blockIdx.x * blockDim.x + threadIdx.x) >> 5;
    int lane = threadIdx.x & 31;
    if (w >= N_TOK) return;
    const float* row = x + (size_t)w * DIM;
    float4 f0 = *(const float4*)&row[lane * 8];
    float4 f1 = *(const float4*)&row[lane * 8 + 4];
    float v[8] = {f0.x, f0.y, f0.z, f0.w, f1.x, f1.y, f1.z, f1.w};
    float m = 0.f;
#pragma unroll
    for (int i = 0; i < 8; i++) m = fmaxf(m, fabsf(v[i]));
    m = warp_max(m);
    float s = 0.f, inv = 0.f;
    if (m > 1e-20f) { s = 127.49f / m; inv = m / 127.49f; }
    __align__(8) signed char q1[8], q2[8];
#pragma unroll
    for (int i = 0; i < 8; i++) quant2(v[i] * s, q1[i], q2[i]);
    size_t o = (size_t)w * DIM + lane * 8;
    *(uint2*)&g_xq1[o] = *(uint2*)q1;
    *(uint2*)&g_xq2[o] = *(uint2*)q2;
    if (lane == 0) g_xs[w] = inv;
}

// w1: one warp per (e, h) column over D=256 (8 per lane, strided)
__global__ void conv_w1_kernel(const float* __restrict__ w1) {
    int w = (blockIdx.x * blockDim.x + threadIdx.x) >> 5;
    int lane = threadIdx.x & 31;
    if (w >= NEXP * HID) return;
    int e = w / HID, h = w - e * HID;
    const float* src = w1 + (size_t)e * DIM * HID + h;
    float v[8];
#pragma unroll
    for (int i = 0; i < 8; i++) v[i] = src[(size_t)(lane * 8 + i) * HID];
    float m = 0.f;
#pragma unroll
    for (int i = 0; i < 8; i++) m = fmaxf(m, fabsf(v[i]));
    m = warp_max(m);
    float s = 0.f, inv = 0.f;
    if (m > 1e-20f) { s = 127.49f / m; inv = m / 127.49f; }
#pragma unroll
    for (int i = 0; i < 8; i++) {
        signed char q1, q2;
        quant2(v[i] * s, q1, q2);
        size_t o = (size_t)e * DIM * HID + (size_t)(lane * 8 + i) * HID + h;
        g_w1q1[o] = q1;
        g_w1q2[o] = q2;
    }
    if (lane == 0) g_w1s[e * HID + h] = inv;
}

// w2: one warp per (e, d) column over HID=512 (16 per lane, strided)
__global__ void conv_w2_kernel(const float* __restrict__ w2) {
    int w = (blockIdx.x * blockDim.x + threadIdx.x) >> 5;
    int lane = threadIdx.x & 31;
    if (w >= NEXP * DIM) return;
    int e = w / DIM, d = w - e * DIM;
    const float* src = w2 + (size_t)e * HID * DIM + d;
    float v[16];
#pragma unroll
    for (int i = 0; i < 16; i++) v[i] = src[(size_t)(lane * 16 + i) * DIM];
    float m = 0.f;
#pragma unroll
    for (int i = 0; i < 16; i++) m = fmaxf(m, fabsf(v[i]));
    m = warp_max(m);
    float s = 0.f, inv = 0.f;
    if (m > 1e-20f) { s = 127.49f / m; inv = m / 127.49f; }
#pragma unroll
    for (int i = 0; i < 16; i++) {
        signed char q1, q2;
        quant2(v[i] * s, q1, q2);
        size_t o = (size_t)e * HID * DIM + (size_t)(lane * 16 + i) * DIM + d;
        g_w2q1[o] = q1;
        g_w2q2[o] = q2;
    }
    if (lane == 0) g_w2s[e * DIM + d] = inv;
}

// ================= third-range helpers =================
__device__ __forceinline__ bool third_range(int third, int bx,
                                            int& t, int& h0pos) {
    int Ts = (g_ntiles + 2) / 3;
    int t0 = third * Ts;
    int tend = min(t0 + Ts, g_ntiles);
    t = t0 + bx;
    if (t >= tend) return false;
    h0pos = g_tile_base[t0];
    return true;
}
__device__ __forceinline__ int third_rows(int third, int& h0pos) {
    int Ts = (g_ntiles + 2) / 3;
    int t0 = min(third * Ts, g_ntiles);
    int tend = min(t0 + Ts, g_ntiles);
    h0pos = (t0 < g_ntiles) ? g_tile_base[t0] : g_off[NEXP];
    int end = (tend < g_ntiles) ? g_tile_base[tend] : g_off[NEXP];
    return end - h0pos;
}

// ================= GEMM1: xq @ w1q -> dequant fp32 g_h ======================
// 512 threads, 16 warps (4x4), warp tile 32x32; dual int accumulators.
__global__ void __launch_bounds__(512)
gemm1_mma(int third) {
    int t, h0pos;
    if (!third_range(third, blockIdx.x, t, h0pos)) return;
    int e = g_tile_e[t], base = g_tile_base[t], rows = g_tile_rows[t];
    int hbase = blockIdx.y * 128;

    __shared__ __align__(16) signed char sA1[128 * LDA];
    __shared__ __align__(16) signed char sA2[128 * LDA];
    __shared__ __align__(16) signed char sB1[KB * LDB];
    __shared__ __align__(16) signed char sB2[KB * LDB];
    __shared__ __align__(16) int stag[16][16][LDS_];

    int tid = threadIdx.x, wid = tid >> 5, lane = tid & 31;
    int wm = wid & 3, wn = wid >> 2;

    const signed char* B1 = g_w1q1 + (size_t)e * DIM * HID;
    const signed char* B2 = g_w1q2 + (size_t)e * DIM * HID;

    wmma::fragment<wmma::accumulator, 16, 16, 16, int> acc1[2][2], acc2[2][2];
#pragma unroll
    for (int i = 0; i < 2; i++)
#pragma unroll
        for (int j = 0; j < 2; j++) {
            wmma::fill_fragment(acc1[i][j], 0);
            wmma::fill_fragment(acc2[i][j], 0);
        }

    // loader roles: tid<256 -> A (row tid>>1, 16 cols), else B
    bool isA = tid < 256;
    int arow = tid >> 1, acol = (tid & 1) * 16;
    int bt = tid - 256, brow = bt >> 3, bcol = (bt & 7) * 16;
    int tok = (isA && arow < rows) ? g_ptok[base + arow] : -1;

    const int NC = DIM / KB;  // 8
    uint4 r1, r2;
    // prefetch chunk 0
    if (isA) {
        r1 = make_uint4(0, 0, 0, 0); r2 = r1;
        if (tok >= 0) {
            size_t s = (size_t)tok * DIM + acol;
            r1 = *(const uint4*)&g_xq1[s];
            r2 = *(const uint4*)&g_xq2[s];
        }
    } else {
        size_t s = (size_t)brow * HID + hbase + bcol;
        r1 = *(const uint4*)&B1[s];
        r2 = *(const uint4*)&B2[s];
    }

    for (int c = 0; c < NC; c++) {
        __syncthreads();
        if (isA) {
            *(uint4*)&sA1[arow * LDA + acol] = r1;
            *(uint4*)&sA2[arow * LDA + acol] = r2;
        } else {
            *(uint4*)&sB1[brow * LDB + bcol] = r1;
            *(uint4*)&sB2[brow * LDB + bcol] = r2;
        }
        __syncthreads();

        if (c + 1 < NC) {
            int k0 = (c + 1) * KB;
            if (isA) {
                r1 = make_uint4(0, 0, 0, 0); r2 = r1;
                if (tok >= 0) {
                    size_t s = (size_t)tok * DIM + k0 + acol;
                    r1 = *(const uint4*)&g_xq1[s];
                    r2 = *(const uint4*)&g_xq2[s];
                }
            } else {
                size_t s = (size_t)(k0 + brow) * HID + hbase + bcol;
                r1 = *(const uint4*)&B1[s];
                r2 = *(const uint4*)&B2[s];
            }
        }

#pragma unroll
        for (int kk = 0; kk < KB / 16; kk++) {
            wmma::fragment<wmma::matrix_a, 16, 16, 16, signed char, wmma::row_major> fa1[2], fa2[2];
#pragma unroll
            for (int i = 0; i < 2; i++) {
                wmma::load_matrix_sync(fa1[i], &sA1[(wm * 32 + i * 16) * LDA + kk * 16], LDA);
                wmma::load_matrix_sync(fa2[i], &sA2[(wm * 32 + i * 16) * LDA + kk * 16], LDA);
            }
#pragma unroll
            for (int j = 0; j < 2; j++) {
                wmma::fragment<wmma::matrix_b, 16, 16, 16, signed char, wmma::row_major> fb1, fb2;
                wmma::load_matrix_sync(fb1, &sB1[kk * 16 * LDB + wn * 32 + j * 16], LDB);
                wmma::load_matrix_sync(fb2, &sB2[kk * 16 * LDB + wn * 32 + j * 16], LDB);
#pragma unroll
                for (int i = 0; i < 2; i++) {
                    wmma::mma_sync(acc1[i][j], fa1[i], fb1, acc1[i][j]);
                    wmma::mma_sync(acc2[i][j], fa1[i], fb2, acc2[i][j]);
                    wmma::mma_sync(acc2[i][j], fa2[i], fb1, acc2[i][j]);
                }
            }
        }
    }

    // epilogue: stag both accs, dequant -> fp32 g_h
    int sr = lane >> 1, sc = (lane & 1) * 8;
#pragma unroll
    for (int i = 0; i < 2; i++)
#pragma unroll
        for (int j = 0; j < 2; j++) {
            int a1[8], a2[8];
            wmma::store_matrix_sync(&stag[wid][0][0], acc1[i][j], LDS_, wmma::mem_row_major);
            __syncwarp();
#pragma unroll
            for (int q = 0; q < 8; q++) a1[q] = stag[wid][sr][sc + q];
            __syncwarp();
            wmma::store_matrix_sync(&stag[wid][0][0], acc2[i][j], LDS_, wmma::mem_row_major);
            __syncwarp();
#pragma unroll
            for (int q = 0; q < 8; q++) a2[q] = stag[wid][sr][sc + q];
            __syncwarp();

            int r_loc = wm * 32 + i * 16 + sr;
            if (r_loc < rows) {
                int tok2 = g_ptok[base + r_loc];
                float inva = g_xs[tok2];
                int c0 = hbase + wn * 32 + j * 16 + sc;
                __align__(16) float v[8];
#pragma unroll
                for (int q = 0; q < 8; q++) {
                    float invb = g_w1s[e * HID + c0 + q];
                    v[q] = ((float)a1[q] + (float)a2[q] * (1.f / 256.f)) * inva * invb;
                }
                size_t ro = (size_t)(base - h0pos + r_loc) * HID + c0;
                *(float4*)&g_h[ro]     = ((float4*)v)[0];
                *(float4*)&g_h[ro + 4] = ((float4*)v)[1];
            }
        }
}

// ================= GELU + quantize h rows (warp per row) =====================
__global__ void __launch_bounds__(256)
gelu_quant_kernel(const float* __restrict__ b1, int third) {
    int h0pos;
    int nrows = third_rows(third, h0pos);
    int w = blockIdx.x * 8 + (threadIdx.x >> 5);
    int lane = threadIdx.x & 31;
    if (w >= nrows) return;
    int pos = h0pos + w;
    int e = 0;
#pragma unroll
    for (int k = 1; k < NEXP; k++) if (pos >= g_off[k]) e = k;
    const float* b1e = b1 + (size_t)e * HID;

    size_t ro = (size_t)w * HID + lane * 16;
    float v[16];
#pragma unroll
    for (int g4 = 0; g4 < 4; g4++) {
        float4 f = *(const float4*)&g_h[ro + g4 * 4];
        v[g4 * 4 + 0] = f.x; v[g4 * 4 + 1] = f.y;
        v[g4 * 4 + 2] = f.z; v[g4 * 4 + 3] = f.w;
    }
    float m = 0.f;
#pragma unroll
    for (int i = 0; i < 16; i++) {
        float z = v[i] + b1e[lane * 16 + i];
        float g = 0.5f * z * (1.0f + erff(z * 0.70710678118654752f));
        v[i] = g;
        m = fmaxf(m, fabsf(g));
    }
    m = warp_max(m);
    float s = 0.f, inv = 0.f;
    if (m > 1e-20f) { s = 127.49f / m; inv = m / 127.49f; }
    __align__(16) signed char q1[16], q2[16];
#pragma unroll
    for (int i = 0; i < 16; i++) quant2(v[i] * s, q1[i], q2[i]);
    *(uint4*)&g_hq1[ro] = *(uint4*)q1;
    *(uint4*)&g_hq2[ro] = *(uint4*)q2;
    if (lane == 0) g_hs[w] = inv;
}

// ================= GEMM2: hq @ w2q -> dequant fp32 g_y ======================
__global__ void __launch_bounds__(512)
gemm2_mma(int third) {
    int t, h0pos;
    if (!third_range(third, blockIdx.x, t, h0pos)) return;
    int e = g_tile_e[t], base = g_tile_base[t], rows = g_tile_rows[t];
    int dbase = blockIdx.y * 128;

    __shared__ __align__(16) signed char sA1[128 * LDA];
    __shared__ __align__(16) signed char sA2[128 * LDA];
    __shared__ __align__(16) signed char sB1[KB * LDB];
    __shared__ __align__(16) signed char sB2[KB * LDB];
    __shared__ __align__(16) int stag[16][16][LDS_];

    int tid = threadIdx.x, wid = tid >> 5, lane = tid & 31;
    int wm = wid & 3, wn = wid >> 2;

    const signed char* B1 = g_w2q1 + (size_t)e * HID * DIM;
    const signed char* B2 = g_w2q2 + (size_t)e * HID * DIM;

    wmma::fragment<wmma::accumulator, 16, 16, 16, int> acc1[2][2], acc2[2][2];
#pragma unroll
    for (int i = 0; i < 2; i++)
#pragma unroll
        for (int j = 0; j < 2; j++) {
            wmma::fill_fragment(acc1[i][j], 0);
            wmma::fill_fragment(acc2[i][j], 0);
        }

    bool isA = tid < 256;
    int arow = tid >> 1, acol = (tid & 1) * 16;
    int bt = tid - 256, brow = bt >> 3, bcol = (bt & 7) * 16;
    bool okA = isA && (arow < rows);
    size_t hrow = (size_t)(base - h0pos + arow) * HID;

    const int NC = HID / KB;  // 16
    uint4 r1, r2;
    if (isA) {
        r1 = make_uint4(0, 0, 0, 0); r2 = r1;
        if (okA) {
            r1 = *(const uint4*)&g_hq1[hrow + acol];
            r2 = *(const uint4*)&g_hq2[hrow + acol];
        }
    } else {
        size_t s = (size_t)brow * DIM + dbase + bcol;
        r1 = *(const uint4*)&B1[s];
        r2 = *(const uint4*)&B2[s];
    }

    for (int c = 0; c < NC; c++) {
        __syncthreads();
        if (isA) {
            *(uint4*)&sA1[arow * LDA + acol] = r1;
            *(uint4*)&sA2[arow * LDA + acol] = r2;
        } else {
            *(uint4*)&sB1[brow * LDB + bcol] = r1;
            *(uint4*)&sB2[brow * LDB + bcol] = r2;
        }
        __syncthreads();

        if (c + 1 < NC) {
            int k0 = (c + 1) * KB;
            if (isA) {
                r1 = make_uint4(0, 0, 0, 0); r2 = r1;
                if (okA) {
                    r1 = *(const uint4*)&g_hq1[hrow + k0 + acol];
                    r2 = *(const uint4*)&g_hq2[hrow + k0 + acol];
                }
            } else {
                size_t s = (size_t)(k0 + brow) * DIM + dbase + bcol;
                r1 = *(const uint4*)&B1[s];
                r2 = *(const uint4*)&B2[s];
            }
        }

#pragma unroll
        for (int kk = 0; kk < KB / 16; kk++) {
            wmma::fragment<wmma::matrix_a, 16, 16, 16, signed char, wmma::row_major> fa1[2], fa2[2];
#pragma unroll
            for (int i = 0; i < 2; i++) {
                wmma::load_matrix_sync(fa1[i], &sA1[(wm * 32 + i * 16) * LDA + kk * 16], LDA);
                wmma::load_matrix_sync(fa2[i], &sA2[(wm * 32 + i * 16) * LDA + kk * 16], LDA);
            }
#pragma unroll
            for (int j = 0; j < 2; j++) {
                wmma::fragment<wmma::matrix_b, 16, 16, 16, signed char, wmma::row_major> fb1, fb2;
                wmma::load_matrix_sync(fb1, &sB1[kk * 16 * LDB + wn * 32 + j * 16], LDB);
                wmma::load_matrix_sync(fb2, &sB2[kk * 16 * LDB + wn * 32 + j * 16], LDB);
#pragma unroll
                for (int i = 0; i < 2; i++) {
                    wmma::mma_sync(acc1[i][j], fa1[i], fb1, acc1[i][j]);
                    wmma::mma_sync(acc2[i][j], fa1[i], fb2, acc2[i][j]);
                    wmma::mma_sync(acc2[i][j], fa2[i], fb1, acc2[i][j]);
                }
            }
        }
    }

    int sr = lane >> 1, sc = (lane & 1) * 8;
#pragma unroll
    for (int i = 0; i < 2; i++)
#pragma unroll
        for (int j = 0; j < 2; j++) {
            int a1[8], a2[8];
            wmma::store_matrix_sync(&stag[wid][0][0], acc1[i][j], LDS_, wmma::mem_row_major);
            __syncwarp();
#pragma unroll
            for (int q = 0; q < 8; q++) a1[q] = stag[wid][sr][sc + q];
            __syncwarp();
            wmma::store_matrix_sync(&stag[wid][0][0], acc2[i][j], LDS_, wmma::mem_row_major);
            __syncwarp();
#pragma unroll
            for (int q = 0; q < 8; q++) a2[q] = stag[wid][sr][sc + q];
            __syncwarp();

            int r_loc = wm * 32 + i * 16 + sr;
            if (r_loc < rows) {
                float inva = g_hs[base - h0pos + r_loc];
                int c0 = dbase + wn * 32 + j * 16 + sc;
                __align__(16) float v[8];
#pragma unroll
                for (int q = 0; q < 8; q++) {
                    float invb = g_w2s[e * DIM + c0 + q];
                    v[q] = ((float)a1[q] + (float)a2[q] * (1.f / 256.f)) * inva * invb;
                }
                size_t ro = (size_t)(base + r_loc) * DIM + c0;
                *(float4*)&g_y[ro]     = ((float4*)v)[0];
                *(float4*)&g_y[ro + 4] = ((float4*)v)[1];
            }
        }
}

// ================= combine: bias + routing weight + sum =================
__global__ void combine_kernel(const float* __restrict__ b2,
                               float* __restrict__ out) {
    int idx = blockIdx.x * blockDim.x + threadIdx.x;
    if (idx >= N_TOK * (DIM / 4)) return;
    int n = idx >> 6, q = idx & 63;
    int p0 = g_tok2pos[2 * n + 0];
    int p1 = g_tok2pos[2 * n + 1];
    int e0 = g_topi[2 * n + 0];
    int e1 = g_topi[2 * n + 1];
    float w0 = g_topw[2 * n + 0];
    float w1 = g_topw[2 * n + 1];
    float4 y0 = ((const float4*)&g_y[(size_t)p0 * DIM])[q];
    float4 y1 = ((const float4*)&g_y[(size_t)p1 * DIM])[q];
    float4 c0 = ((const float4*)&b2[(size_t)e0 * DIM])[q];
    float4 c1 = ((const float4*)&b2[(size_t)e1 * DIM])[q];
    float4 r;
    r.x = w0 * (y0.x + c0.x) + w1 * (y1.x + c1.x);
    r.y = w0 * (y0.y + c0.y) + w1 * (y1.y + c1.y);
    r.z = w0 * (y0.z + c0.z) + w1 * (y1.z + c1.z);
    r.w = w0 * (y0.w + c0.w) + w1 * (y1.w + c1.w);
    ((float4*)out)[(size_t)n * 64 + q] = r;
}

// ================= launch =================
extern "C" void kernel_launch(void* const* d_in, const int* in_sizes, int n_in,
                              void* d_out, int out_size) {
    const float* x  = (const float*)d_in[0];
    const float* Wg = (const float*)d_in[1];
    const float* w1 = (const float*)d_in[2];
    const float* b1 = (const float*)d_in[3];
    const float* w2 = (const float*)d_in[4];
    const float* b2 = (const float*)d_in[5];
    float* out = (float*)d_out;

    init_kernel<<<1, 32>>>();
    gate_kernel<<<N_TOK / 4, 128>>>(x, Wg);
    prep_kernel<<<1, 1>>>();
    scatter_kernel<<<NASSIGN / 256, 256>>>();
    conv_x_kernel<<<N_TOK * 32 / 256, 256>>>(x);
    conv_w1_kernel<<<NEXP * HID * 32 / 256, 256>>>(w1);
    conv_w2_kernel<<<NEXP * DIM * 32 / 256, 256>>>(w2);
    for (int third = 0; third < 3; third++) {
        gemm1_mma<<<dim3(T_TILES, HID / 128), 512>>>(third);
        gelu_quant_kernel<<<(HROWS + 7) / 8, 256>>>(b1, third);
        gemm2_mma<<<dim3(T_TILES, DIM / 128), 512>>>(third);
    }
    combine_kernel<<<(N_TOK * (DIM / 4)) / 256, 256>>>(b2, out);
}

// round 16
// speedup vs baseline: 3.3928x; 3.3928x over previous
#include <cuda_runtime.h>
#include <cuda_bf16.h>
#include <mma.h>
#include <math.h>
#include <stdint.h>

using namespace nvcuda;

// Problem constants
#define N_TOK 16384
#define DIM   256
#define NEXP  8
#define HID   512
#define TOPK  2
#define NASSIGN (N_TOK * TOPK)            // 32768
#define NPAD (NASSIGN + NEXP * 128)       // 33792 padded positions
#define MAX_TILES (NPAD / 128)            // 264
#define HALF_TILES 136
#define HROWS 17408                       // per-half h rows (136*128)

// GEMM tiling: CTA tile 128x128, K chunk 32, wmma 16x16x16, 16 warps (32x32).
#define KB   32
#define LDA  40        // A smem leading dim (bf16)
#define LDB  136       // B smem leading dim (bf16)

// ================= device scratch =================
__device__ int   g_counts[NEXP];
__device__ int   g_cursor[NEXP];
__device__ int   g_off[NEXP + 1];
__device__ int   g_ntiles;
__device__ int   g_tile_e[MAX_TILES];
__device__ int   g_tile_base[MAX_TILES];
__device__ int   g_tile_rows[MAX_TILES];

__device__ int   g_topi[NASSIGN];
__device__ float g_topw[NASSIGN];
__device__ int   g_ptok[NPAD];
__device__ int   g_tok2pos[NASSIGN];

__device__ __nv_bfloat16 g_xhi[(size_t)N_TOK * DIM];
__device__ __nv_bfloat16 g_xlo[(size_t)N_TOK * DIM];
__device__ __nv_bfloat16 g_w1hi[(size_t)NEXP * DIM * HID];  // [E][D][H]
__device__ __nv_bfloat16 g_w1lo[(size_t)NEXP * DIM * HID];
__device__ __nv_bfloat16 g_w2hi[(size_t)NEXP * HID * DIM];  // [E][H][D]
__device__ __nv_bfloat16 g_w2lo[(size_t)NEXP * HID * DIM];
// g_h: raw fp32 from GEMM1, then packed (bf16 hi | bf16 lo) in place by gelu
__device__ unsigned int g_h[(size_t)HROWS * HID];
__device__ float g_y[(size_t)NPAD * DIM];

// ================= kernel 0: init =================
__global__ void init_kernel() {
    int t = threadIdx.x;
    if (t < NEXP) { g_counts[t] = 0; g_cursor[t] = 0; }
}

// ================= kernel 1: gate (top-2 + softmax) =================
__global__ void gate_kernel(const float* __restrict__ x,
                            const float* __restrict__ Wg) {
    __shared__ float sWg[NEXP][DIM];
    int tid = threadIdx.x;
    for (int i = tid; i < DIM * NEXP; i += blockDim.x) {
        int e = i & (NEXP - 1);
        int d = i >> 3;
        sWg[e][d] = Wg[i];
    }
    __syncthreads();

    int warp = tid >> 5, lane = tid & 31;
    int n = blockIdx.x * 4 + warp;
    if (n >= N_TOK) return;

    float lg[NEXP];
#pragma unroll
    for (int e = 0; e < NEXP; e++) lg[e] = 0.f;
#pragma unroll
    for (int j = 0; j < 8; j++) {
        int d = lane + 32 * j;
        float xv = x[(size_t)n * DIM + d];
#pragma unroll
        for (int e = 0; e < NEXP; e++) lg[e] += xv * sWg[e][d];
    }
#pragma unroll
    for (int e = 0; e < NEXP; e++)
#pragma unroll
        for (int o = 16; o > 0; o >>= 1)
            lg[e] += __shfl_xor_sync(0xffffffffu, lg[e], o);

    if (lane == 0) {
        float m1 = lg[0]; int i1 = 0;
#pragma unroll
        for (int e = 1; e < NEXP; e++) if (lg[e] > m1) { m1 = lg[e]; i1 = e; }
        float m2 = -1e30f; int i2 = 0;
#pragma unroll
        for (int e = 0; e < NEXP; e++)
            if (e != i1 && lg[e] > m2) { m2 = lg[e]; i2 = e; }
        float p2 = expf(m2 - m1);
        float inv = 1.f / (1.f + p2);
        g_topi[2 * n + 0] = i1;  g_topw[2 * n + 0] = inv;
        g_topi[2 * n + 1] = i2;  g_topw[2 * n + 1] = p2 * inv;
        atomicAdd(&g_counts[i1], 1);
        atomicAdd(&g_counts[i2], 1);
    }
}

// ================= kernel 2: prefix (128-aligned) + tile descriptors ========
__global__ void prep_kernel() {
    int off = 0;
    for (int e = 0; e < NEXP; e++) {
        g_off[e] = off;
        off += (g_counts[e] + 127) & ~127;
    }
    g_off[NEXP] = off;
    int t = 0;
    for (int e = 0; e < NEXP; e++) {
        int cnt = g_counts[e];
        for (int s = 0; s < cnt; s += 128) {
            g_tile_e[t] = e;
            g_tile_base[t] = g_off[e] + s;
            g_tile_rows[t] = min(128, cnt - s);
            t++;
        }
    }
    g_ntiles = t;
}

// ================= kernel 3: scatter =================
__global__ void scatter_kernel() {
    int idx = blockIdx.x * blockDim.x + threadIdx.x;
    if (idx >= NASSIGN) return;
    int e = g_topi[idx];
    int pos = g_off[e] + atomicAdd(&g_cursor[e], 1);
    g_ptok[pos] = idx >> 1;
    g_tok2pos[idx] = pos;
}

// ===== split helper =====
__device__ __forceinline__ void split8(const float* v,
                                       __nv_bfloat16* h, __nv_bfloat16* l) {
#pragma unroll
    for (int i = 0; i < 8; i++) {
        h[i] = __float2bfloat16(v[i]);
        l[i] = __float2bfloat16(v[i] - __bfloat162float(h[i]));
    }
}

// ================= conv kernels (globals referenced INSIDE device code) ======
__global__ void conv_x_kernel(const float* __restrict__ src) {
    int idx = blockIdx.x * blockDim.x + threadIdx.x;
    if (idx >= N_TOK * DIM / 8) return;
    size_t b8 = (size_t)idx * 8;
    float4 a = *(const float4*)&src[b8];
    float4 b = *(const float4*)&src[b8 + 4];
    float v[8] = {a.x, a.y, a.z, a.w, b.x, b.y, b.z, b.w};
    __align__(16) __nv_bfloat16 h[8], l[8];
    split8(v, h, l);
    *(uint4*)&g_xhi[b8] = *(uint4*)h;
    *(uint4*)&g_xlo[b8] = *(uint4*)l;
}

__global__ void conv_w1_kernel(const float* __restrict__ src) {
    int idx = blockIdx.x * blockDim.x + threadIdx.x;
    if (idx >= NEXP * DIM * HID / 8) return;
    size_t b8 = (size_t)idx * 8;
    float4 a = *(const float4*)&src[b8];
    float4 b = *(const float4*)&src[b8 + 4];
    float v[8] = {a.x, a.y, a.z, a.w, b.x, b.y, b.z, b.w};
    __align__(16) __nv_bfloat16 h[8], l[8];
    split8(v, h, l);
    *(uint4*)&g_w1hi[b8] = *(uint4*)h;
    *(uint4*)&g_w1lo[b8] = *(uint4*)l;
}

__global__ void conv_w2_kernel(const float* __restrict__ src) {
    int idx = blockIdx.x * blockDim.x + threadIdx.x;
    if (idx >= NEXP * HID * DIM / 8) return;
    size_t b8 = (size_t)idx * 8;
    float4 a = *(const float4*)&src[b8];
    float4 b = *(const float4*)&src[b8 + 4];
    float v[8] = {a.x, a.y, a.z, a.w, b.x, b.y, b.z, b.w};
    __align__(16) __nv_bfloat16 h[8], l[8];
    split8(v, h, l);
    *(uint4*)&g_w2hi[b8] = *(uint4*)h;
    *(uint4*)&g_w2lo[b8] = *(uint4*)l;
}

// ================= half-range helpers =================
__device__ __forceinline__ bool tile_range(int half, int bx,
                                           int& t, int& h0pos) {
    int Hs = (g_ntiles + 1) >> 1;
    int t0 = half ? Hs : 0;
    int tend = half ? g_ntiles : Hs;
    t = t0 + bx;
    if (t >= tend) return false;
    h0pos = g_tile_base[t0];
    return true;
}
__device__ __forceinline__ void half_rows(int half, int& h0, int& hend) {
    int Hs = (g_ntiles + 1) >> 1;
    h0 = half ? g_tile_base[Hs] : 0;
    hend = half ? g_off[NEXP] : g_tile_base[Hs];
}

// ================= GEMM1: x @ w1[e] -> raw fp32 g_h ==========================
// 512 threads = 16 warps (4x4), warp tile 32x32; A/B loader role split + prefetch.
__global__ void __launch_bounds__(512)
gemm1_mma(int half) {
    int t, h0pos;
    if (!tile_range(half, blockIdx.x, t, h0pos)) return;
    int e = g_tile_e[t], base = g_tile_base[t], rows = g_tile_rows[t];
    int hbase = blockIdx.y * 128;

    __shared__ __align__(16) __nv_bfloat16 sAh[128 * LDA];
    __shared__ __align__(16) __nv_bfloat16 sAl[128 * LDA];
    __shared__ __align__(16) __nv_bfloat16 sBh[KB * LDB];
    __shared__ __align__(16) __nv_bfloat16 sBl[KB * LDB];

    int tid = threadIdx.x, wid = tid >> 5;
    int wm = wid & 3, wn = wid >> 2;   // rows wm*32..+31, cols wn*32..+31

    const __nv_bfloat16* w1h = g_w1hi + (size_t)e * DIM * HID;
    const __nv_bfloat16* w1l = g_w1lo + (size_t)e * DIM * HID;

    wmma::fragment<wmma::accumulator, 16, 16, 16, float> acc[2][2];
#pragma unroll
    for (int i = 0; i < 2; i++)
#pragma unroll
        for (int j = 0; j < 2; j++) wmma::fill_fragment(acc[i][j], 0.f);

    // loader roles: tid<256 -> A, tid>=256 -> B
    bool isA = tid < 256;
    int arow = tid >> 1, acol = (tid & 1) * 16;
    int bt = tid - 256, brow = bt >> 3, bcol = (bt & 7) * 16;
    int tok = (isA && arow < rows) ? g_ptok[base + arow] : -1;

    const int NC = DIM / KB;
    uint4 r0, r1, r2, r3;   // (hi0, hi1, lo0, lo1)

    // prefetch chunk 0
    if (isA) {
        r0 = r1 = r2 = r3 = make_uint4(0, 0, 0, 0);
        if (tok >= 0) {
            size_t s = (size_t)tok * DIM + acol;
            r0 = *(const uint4*)&g_xhi[s];
            r1 = *(const uint4*)&g_xhi[s + 8];
            r2 = *(const uint4*)&g_xlo[s];
            r3 = *(const uint4*)&g_xlo[s + 8];
        }
    } else {
        size_t s = (size_t)brow * HID + hbase + bcol;
        r0 = *(const uint4*)&w1h[s];
        r1 = *(const uint4*)&w1h[s + 8];
        r2 = *(const uint4*)&w1l[s];
        r3 = *(const uint4*)&w1l[s + 8];
    }

    for (int c = 0; c < NC; c++) {
        __syncthreads();
        if (isA) {
            *(uint4*)&sAh[arow * LDA + acol]     = r0;
            *(uint4*)&sAh[arow * LDA + acol + 8] = r1;
            *(uint4*)&sAl[arow * LDA + acol]     = r2;
            *(uint4*)&sAl[arow * LDA + acol + 8] = r3;
        } else {
            *(uint4*)&sBh[brow * LDB + bcol]     = r0;
            *(uint4*)&sBh[brow * LDB + bcol + 8] = r1;
            *(uint4*)&sBl[brow * LDB + bcol]     = r2;
            *(uint4*)&sBl[brow * LDB + bcol + 8] = r3;
        }
        __syncthreads();

        if (c + 1 < NC) {
            int k0 = (c + 1) * KB;
            if (isA) {
                r0 = r1 = r2 = r3 = make_uint4(0, 0, 0, 0);
                if (tok >= 0) {
                    size_t s = (size_t)tok * DIM + k0 + acol;
                    r0 = *(const uint4*)&g_xhi[s];
                    r1 = *(const uint4*)&g_xhi[s + 8];
                    r2 = *(const uint4*)&g_xlo[s];
                    r3 = *(const uint4*)&g_xlo[s + 8];
                }
            } else {
                size_t s = (size_t)(k0 + brow) * HID + hbase + bcol;
                r0 = *(const uint4*)&w1h[s];
                r1 = *(const uint4*)&w1h[s + 8];
                r2 = *(const uint4*)&w1l[s];
                r3 = *(const uint4*)&w1l[s + 8];
            }
        }

#pragma unroll
        for (int kk = 0; kk < KB / 16; kk++) {
            wmma::fragment<wmma::matrix_a, 16, 16, 16, __nv_bfloat16, wmma::row_major> fah[2], fal[2];
#pragma unroll
            for (int i = 0; i < 2; i++) {
                wmma::load_matrix_sync(fah[i], &sAh[(wm * 32 + i * 16) * LDA + kk * 16], LDA);
                wmma::load_matrix_sync(fal[i], &sAl[(wm * 32 + i * 16) * LDA + kk * 16], LDA);
            }
#pragma unroll
            for (int j = 0; j < 2; j++) {
                wmma::fragment<wmma::matrix_b, 16, 16, 16, __nv_bfloat16, wmma::row_major> fbh, fbl;
                wmma::load_matrix_sync(fbh, &sBh[kk * 16 * LDB + wn * 32 + j * 16], LDB);
                wmma::load_matrix_sync(fbl, &sBl[kk * 16 * LDB + wn * 32 + j * 16], LDB);
#pragma unroll
                for (int i = 0; i < 2; i++) {
                    wmma::mma_sync(acc[i][j], fah[i], fbh, acc[i][j]);
                    wmma::mma_sync(acc[i][j], fal[i], fbh, acc[i][j]);
                    wmma::mma_sync(acc[i][j], fah[i], fbl, acc[i][j]);
                }
            }
        }
    }

    // direct stores: tile exclusively owns its 128 g_h rows (padded segments)
#pragma unroll
    for (int i = 0; i < 2; i++)
#pragma unroll
        for (int j = 0; j < 2; j++) {
            size_t ro = (size_t)(base - h0pos + wm * 32 + i * 16) * HID
                      + hbase + wn * 32 + j * 16;
            wmma::store_matrix_sync((float*)&g_h[ro], acc[i][j], HID,
                                    wmma::mem_row_major);
        }
}

// ================= GELU + in-place pack (fp32 -> bf16 hi|lo) =================
__global__ void __launch_bounds__(256)
gelu_pack_kernel(const float* __restrict__ b1, int half) {
    int h0, hend;
    half_rows(half, h0, hend);
    int nquads = (hend - h0) * (HID / 4);
    int idx = blockIdx.x * blockDim.x + threadIdx.x;
    if (idx >= nquads) return;
    int rowo = idx / (HID / 4);
    int q = idx - rowo * (HID / 4);
    int pos = h0 + rowo;
    int e = 0;
#pragma unroll
    for (int k = 1; k < NEXP; k++) if (pos >= g_off[k]) e = k;
    const float* b1e = b1 + (size_t)e * HID + q * 4;
    size_t o = (size_t)rowo * HID + q * 4;
    float4 z4 = *(const float4*)&g_h[o];
    float zz[4] = {z4.x, z4.y, z4.z, z4.w};
    unsigned int pk[4];
#pragma unroll
    for (int i = 0; i < 4; i++) {
        float z = zz[i] + b1e[i];
        float g = 0.5f * z * (1.0f + erff(z * 0.70710678118654752f));
        __nv_bfloat16 h = __float2bfloat16(g);
        __nv_bfloat16 l = __float2bfloat16(g - __bfloat162float(h));
        unsigned short hu = *(unsigned short*)&h;
        unsigned short lu = *(unsigned short*)&l;
        pk[i] = (unsigned int)hu | ((unsigned int)lu << 16);
    }
    *(uint4*)&g_h[o] = *(uint4*)pk;
}

// ================= GEMM2: h @ w2[e] -> raw fp32 g_y ==========================
__global__ void __launch_bounds__(512)
gemm2_mma(int half) {
    int t, h0pos;
    if (!tile_range(half, blockIdx.x, t, h0pos)) return;
    int e = g_tile_e[t], base = g_tile_base[t], rows = g_tile_rows[t];
    int dbase = blockIdx.y * 128;

    __shared__ __align__(16) __nv_bfloat16 sAh[128 * LDA];
    __shared__ __align__(16) __nv_bfloat16 sAl[128 * LDA];
    __shared__ __align__(16) __nv_bfloat16 sBh[KB * LDB];
    __shared__ __align__(16) __nv_bfloat16 sBl[KB * LDB];

    int tid = threadIdx.x, wid = tid >> 5;
    int wm = wid & 3, wn = wid >> 2;

    const __nv_bfloat16* w2h = g_w2hi + (size_t)e * HID * DIM;
    const __nv_bfloat16* w2l = g_w2lo + (size_t)e * HID * DIM;

    wmma::fragment<wmma::accumulator, 16, 16, 16, float> acc[2][2];
#pragma unroll
    for (int i = 0; i < 2; i++)
#pragma unroll
        for (int j = 0; j < 2; j++) wmma::fill_fragment(acc[i][j], 0.f);

    bool isA = tid < 256;
    int arow = tid >> 1, acol = (tid & 1) * 16;
    int bt = tid - 256, brow = bt >> 3, bcol = (bt & 7) * 16;
    bool okA = isA && (arow < rows);
    size_t hrow = (size_t)(base - h0pos + arow) * HID;

    const int NC = HID / KB;
    uint4 p0, p1, p2, p3;   // A: 16 packed words; B: hi0,hi1,lo0,lo1

    if (isA) {
        p0 = p1 = p2 = p3 = make_uint4(0, 0, 0, 0);
        if (okA) {
            p0 = *(const uint4*)&g_h[hrow + acol];
            p1 = *(const uint4*)&g_h[hrow + acol + 4];
            p2 = *(const uint4*)&g_h[hrow + acol + 8];
            p3 = *(const uint4*)&g_h[hrow + acol + 12];
        }
    } else {
        size_t s = (size_t)brow * DIM + dbase + bcol;
        p0 = *(const uint4*)&w2h[s];
        p1 = *(const uint4*)&w2h[s + 8];
        p2 = *(const uint4*)&w2l[s];
        p3 = *(const uint4*)&w2l[s + 8];
    }

    for (int c = 0; c < NC; c++) {
        __syncthreads();
        if (isA) {
            unsigned int w[16] = {p0.x, p0.y, p0.z, p0.w, p1.x, p1.y, p1.z, p1.w,
                                  p2.x, p2.y, p2.z, p2.w, p3.x, p3.y, p3.z, p3.w};
            unsigned int hw[8], lw[8];
#pragma unroll
            for (int g = 0; g < 8; g++) {
                hw[g] = __byte_perm(w[2 * g], w[2 * g + 1], 0x5410);
                lw[g] = __byte_perm(w[2 * g], w[2 * g + 1], 0x7632);
            }
            *(uint4*)&sAh[arow * LDA + acol]     = *(uint4*)&hw[0];
            *(uint4*)&sAh[arow * LDA + acol + 8] = *(uint4*)&hw[4];
            *(uint4*)&sAl[arow * LDA + acol]     = *(uint4*)&lw[0];
            *(uint4*)&sAl[arow * LDA + acol + 8] = *(uint4*)&lw[4];
        } else {
            *(uint4*)&sBh[brow * LDB + bcol]     = p0;
            *(uint4*)&sBh[brow * LDB + bcol + 8] = p1;
            *(uint4*)&sBl[brow * LDB + bcol]     = p2;
            *(uint4*)&sBl[brow * LDB + bcol + 8] = p3;
        }
        __syncthreads();

        if (c + 1 < NC) {
            int k0 = (c + 1) * KB;
            if (isA) {
                p0 = p1 = p2 = p3 = make_uint4(0, 0, 0, 0);
                if (okA) {
                    p0 = *(const uint4*)&g_h[hrow + k0 + acol];
                    p1 = *(const uint4*)&g_h[hrow + k0 + acol + 4];
                    p2 = *(const uint4*)&g_h[hrow + k0 + acol + 8];
                    p3 = *(const uint4*)&g_h[hrow + k0 + acol + 12];
                }
            } else {
                size_t s = (size_t)(k0 + brow) * DIM + dbase + bcol;
                p0 = *(const uint4*)&w2h[s];
                p1 = *(const uint4*)&w2h[s + 8];
                p2 = *(const uint4*)&w2l[s];
                p3 = *(const uint4*)&w2l[s + 8];
            }
        }

#pragma unroll
        for (int kk = 0; kk < KB / 16; kk++) {
            wmma::fragment<wmma::matrix_a, 16, 16, 16, __nv_bfloat16, wmma::row_major> fah[2], fal[2];
#pragma unroll
            for (int i = 0; i < 2; i++) {
                wmma::load_matrix_sync(fah[i], &sAh[(wm * 32 + i * 16) * LDA + kk * 16], LDA);
                wmma::load_matrix_sync(fal[i], &sAl[(wm * 32 + i * 16) * LDA + kk * 16], LDA);
            }
#pragma unroll
            for (int j = 0; j < 2; j++) {
                wmma::fragment<wmma::matrix_b, 16, 16, 16, __nv_bfloat16, wmma::row_major> fbh, fbl;
                wmma::load_matrix_sync(fbh, &sBh[kk * 16 * LDB + wn * 32 + j * 16], LDB);
                wmma::load_matrix_sync(fbl, &sBl[kk * 16 * LDB + wn * 32 + j * 16], LDB);
#pragma unroll
                for (int i = 0; i < 2; i++) {
                    wmma::mma_sync(acc[i][j], fah[i], fbh, acc[i][j]);
                    wmma::mma_sync(acc[i][j], fal[i], fbh, acc[i][j]);
                    wmma::mma_sync(acc[i][j], fah[i], fbl, acc[i][j]);
                }
            }
        }
    }

#pragma unroll
    for (int i = 0; i < 2; i++)
#pragma unroll
        for (int j = 0; j < 2; j++) {
            size_t ro = (size_t)(base + wm * 32 + i * 16) * DIM
                      + dbase + wn * 32 + j * 16;
            wmma::store_matrix_sync(&g_y[ro], acc[i][j], DIM, wmma::mem_row_major);
        }
}

// ================= combine: bias + routing weight + sum =================
__global__ void combine_kernel(const float* __restrict__ b2,
                               float* __restrict__ out) {
    int idx = blockIdx.x * blockDim.x + threadIdx.x;
    if (idx >= N_TOK * (DIM / 4)) return;
    int n = idx >> 6, q = idx & 63;
    int p0 = g_tok2pos[2 * n + 0];
    int p1 = g_tok2pos[2 * n + 1];
    int e0 = g_topi[2 * n + 0];
    int e1 = g_topi[2 * n + 1];
    float w0 = g_topw[2 * n + 0];
    float w1 = g_topw[2 * n + 1];
    float4 y0 = ((const float4*)&g_y[(size_t)p0 * DIM])[q];
    float4 y1 = ((const float4*)&g_y[(size_t)p1 * DIM])[q];
    float4 c0 = ((const float4*)&b2[(size_t)e0 * DIM])[q];
    float4 c1 = ((const float4*)&b2[(size_t)e1 * DIM])[q];
    float4 r;
    r.x = w0 * (y0.x + c0.x) + w1 * (y1.x + c1.x);
    r.y = w0 * (y0.y + c0.y) + w1 * (y1.y + c1.y);
    r.z = w0 * (y0.z + c0.z) + w1 * (y1.z + c1.z);
    r.w = w0 * (y0.w + c0.w) + w1 * (y1.w + c1.w);
    ((float4*)out)[(size_t)n * 64 + q] = r;
}

// ================= launch =================
extern "C" void kernel_launch(void* const* d_in, const int* in_sizes, int n_in,
                              void* d_out, int out_size) {
    const float* x  = (const float*)d_in[0];
    const float* Wg = (const float*)d_in[1];
    const float* w1 = (const float*)d_in[2];
    const float* b1 = (const float*)d_in[3];
    const float* w2 = (const float*)d_in[4];
    const float* b2 = (const float*)d_in[5];
    float* out = (float*)d_out;

    init_kernel<<<1, 32>>>();
    gate_kernel<<<N_TOK / 4, 128>>>(x, Wg);
    prep_kernel<<<1, 1>>>();
    scatter_kernel<<<NASSIGN / 256, 256>>>();
    conv_x_kernel<<<(N_TOK * DIM / 8) / 256, 256>>>(x);
    conv_w1_kernel<<<(NEXP * DIM * HID / 8) / 256, 256>>>(w1);
    conv_w2_kernel<<<(NEXP * HID * DIM / 8) / 256, 256>>>(w2);
    int gelu_blocks = (HROWS * (HID / 4) + 255) / 256;
    for (int half = 0; half < 2; half++) {
        gemm1_mma<<<dim3(HALF_TILES, HID / 128), 512>>>(half);
        gelu_pack_kernel<<<gelu_blocks, 256>>>(b1, half);
        gemm2_mma<<<dim3(HALF_TILES, DIM / 128), 512>>>(half);
    }
    combine_kernel<<<(N_TOK * (DIM / 4)) / 256, 256>>>(b2, out);
}

// round 17
// speedup vs baseline: 4.1810x; 1.2323x over previous
#include <cuda_runtime.h>
#include <cuda_fp16.h>
#include <mma.h>
#include <math.h>
#include <stdint.h>

using namespace nvcuda;

// Problem constants
#define N_TOK 16384
#define DIM   256
#define NEXP  8
#define HID   512
#define TOPK  2
#define NASSIGN (N_TOK * TOPK)            // 32768
#define NPAD (NASSIGN + NEXP * 128)       // 33792 padded positions
#define MAX_TILES (NPAD / 128)            // 264
#define HALF_TILES 136
#define HROWS 17408                       // per-half h rows (136*128)

// GEMM tiling: CTA tile 128x128, K chunk 32, wmma 16x16x16, 8 warps (32x64).
#define KB   32
#define LDA  40        // A smem leading dim (fp16)
#define LDB  136       // B smem leading dim (fp16)

// ================= device scratch =================
__device__ int   g_counts[NEXP];
__device__ int   g_cursor[NEXP];
__device__ int   g_off[NEXP + 1];
__device__ int   g_ntiles;
__device__ int   g_tile_e[MAX_TILES];
__device__ int   g_tile_base[MAX_TILES];
__device__ int   g_tile_rows[MAX_TILES];

__device__ int   g_topi[NASSIGN];
__device__ float g_topw[NASSIGN];
__device__ int   g_ptok[NPAD];
__device__ int   g_tok2pos[NASSIGN];

__device__ __half g_xhi[(size_t)N_TOK * DIM];
__device__ __half g_xlo[(size_t)N_TOK * DIM];
__device__ __half g_w1hi[(size_t)NEXP * DIM * HID];  // [E][D][H]
__device__ __half g_w1lo[(size_t)NEXP * DIM * HID];
__device__ __half g_w2hi[(size_t)NEXP * HID * DIM];  // [E][H][D]
__device__ __half g_w2lo[(size_t)NEXP * HID * DIM];
// g_h: raw fp32 main accum from GEMM1, then packed (f16 hi | f16 lo) in place
__device__ unsigned int g_h[(size_t)HROWS * HID];
__device__ __half g_hres[(size_t)HROWS * HID];       // f16 residual accum
__device__ float  g_y[(size_t)NPAD * DIM];
__device__ __half g_yres[(size_t)NPAD * DIM];

// ================= kernel 0: init =================
__global__ void init_kernel() {
    int t = threadIdx.x;
    if (t < NEXP) { g_counts[t] = 0; g_cursor[t] = 0; }
}

// ================= kernel 1: gate (top-2 + softmax) =================
__global__ void gate_kernel(const float* __restrict__ x,
                            const float* __restrict__ Wg) {
    __shared__ float sWg[NEXP][DIM];
    int tid = threadIdx.x;
    for (int i = tid; i < DIM * NEXP; i += blockDim.x) {
        int e = i & (NEXP - 1);
        int d = i >> 3;
        sWg[e][d] = Wg[i];
    }
    __syncthreads();

    int warp = tid >> 5, lane = tid & 31;
    int n = blockIdx.x * 4 + warp;
    if (n >= N_TOK) return;

    float lg[NEXP];
#pragma unroll
    for (int e = 0; e < NEXP; e++) lg[e] = 0.f;
#pragma unroll
    for (int j = 0; j < 8; j++) {
        int d = lane + 32 * j;
        float xv = x[(size_t)n * DIM + d];
#pragma unroll
        for (int e = 0; e < NEXP; e++) lg[e] += xv * sWg[e][d];
    }
#pragma unroll
    for (int e = 0; e < NEXP; e++)
#pragma unroll
        for (int o = 16; o > 0; o >>= 1)
            lg[e] += __shfl_xor_sync(0xffffffffu, lg[e], o);

    if (lane == 0) {
        float m1 = lg[0]; int i1 = 0;
#pragma unroll
        for (int e = 1; e < NEXP; e++) if (lg[e] > m1) { m1 = lg[e]; i1 = e; }
        float m2 = -1e30f; int i2 = 0;
#pragma unroll
        for (int e = 0; e < NEXP; e++)
            if (e != i1 && lg[e] > m2) { m2 = lg[e]; i2 = e; }
        float p2 = expf(m2 - m1);
        float inv = 1.f / (1.f + p2);
        g_topi[2 * n + 0] = i1;  g_topw[2 * n + 0] = inv;
        g_topi[2 * n + 1] = i2;  g_topw[2 * n + 1] = p2 * inv;
        atomicAdd(&g_counts[i1], 1);
        atomicAdd(&g_counts[i2], 1);
    }
}

// ================= kernel 2: prefix (128-aligned) + tile descriptors ========
__global__ void prep_kernel() {
    int off = 0;
    for (int e = 0; e < NEXP; e++) {
        g_off[e] = off;
        off += (g_counts[e] + 127) & ~127;
    }
    g_off[NEXP] = off;
    int t = 0;
    for (int e = 0; e < NEXP; e++) {
        int cnt = g_counts[e];
        for (int s = 0; s < cnt; s += 128) {
            g_tile_e[t] = e;
            g_tile_base[t] = g_off[e] + s;
            g_tile_rows[t] = min(128, cnt - s);
            t++;
        }
    }
    g_ntiles = t;
}

// ================= kernel 3: scatter =================
__global__ void scatter_kernel() {
    int idx = blockIdx.x * blockDim.x + threadIdx.x;
    if (idx >= NASSIGN) return;
    int e = g_topi[idx];
    int pos = g_off[e] + atomicAdd(&g_cursor[e], 1);
    g_ptok[pos] = idx >> 1;
    g_tok2pos[idx] = pos;
}

// ===== split helper: fp32 -> fp16 hi + lo =====
__device__ __forceinline__ void split8h(const float* v, __half* h, __half* l) {
#pragma unroll
    for (int i = 0; i < 8; i++) {
        h[i] = __float2half(v[i]);
        l[i] = __float2half(v[i] - __half2float(h[i]));
    }
}

// ================= conv kernels (globals referenced INSIDE device code) ======
__global__ void conv_x_kernel(const float* __restrict__ src) {
    int idx = blockIdx.x * blockDim.x + threadIdx.x;
    if (idx >= N_TOK * DIM / 8) return;
    size_t b8 = (size_t)idx * 8;
    float4 a = *(const float4*)&src[b8];
    float4 b = *(const float4*)&src[b8 + 4];
    float v[8] = {a.x, a.y, a.z, a.w, b.x, b.y, b.z, b.w};
    __align__(16) __half h[8], l[8];
    split8h(v, h, l);
    *(uint4*)&g_xhi[b8] = *(uint4*)h;
    *(uint4*)&g_xlo[b8] = *(uint4*)l;
}

__global__ void conv_w1_kernel(const float* __restrict__ src) {
    int idx = blockIdx.x * blockDim.x + threadIdx.x;
    if (idx >= NEXP * DIM * HID / 8) return;
    size_t b8 = (size_t)idx * 8;
    float4 a = *(const float4*)&src[b8];
    float4 b = *(const float4*)&src[b8 + 4];
    float v[8] = {a.x, a.y, a.z, a.w, b.x, b.y, b.z, b.w};
    __align__(16) __half h[8], l[8];
    split8h(v, h, l);
    *(uint4*)&g_w1hi[b8] = *(uint4*)h;
    *(uint4*)&g_w1lo[b8] = *(uint4*)l;
}

__global__ void conv_w2_kernel(const float* __restrict__ src) {
    int idx = blockIdx.x * blockDim.x + threadIdx.x;
    if (idx >= NEXP * HID * DIM / 8) return;
    size_t b8 = (size_t)idx * 8;
    float4 a = *(const float4*)&src[b8];
    float4 b = *(const float4*)&src[b8 + 4];
    float v[8] = {a.x, a.y, a.z, a.w, b.x, b.y, b.z, b.w};
    __align__(16) __half h[8], l[8];
    split8h(v, h, l);
    *(uint4*)&g_w2hi[b8] = *(uint4*)h;
    *(uint4*)&g_w2lo[b8] = *(uint4*)l;
}

// ================= half-range helpers =================
__device__ __forceinline__ bool tile_range(int half_, int bx,
                                           int& t, int& h0pos) {
    int Hs = (g_ntiles + 1) >> 1;
    int t0 = half_ ? Hs : 0;
    int tend = half_ ? g_ntiles : Hs;
    t = t0 + bx;
    if (t >= tend) return false;
    h0pos = g_tile_base[t0];
    return true;
}
__device__ __forceinline__ void half_rows(int half_, int& h0, int& hend) {
    int Hs = (g_ntiles + 1) >> 1;
    h0 = half_ ? g_tile_base[Hs] : 0;
    hend = half_ ? g_off[NEXP] : g_tile_base[Hs];
}

// ================= GEMM1: x @ w1[e] -> f32 main (g_h) + f16 res (g_hres) =====
__global__ void __launch_bounds__(256)
gemm1_mma(int half_) {
    int t, h0pos;
    if (!tile_range(half_, blockIdx.x, t, h0pos)) return;
    int e = g_tile_e[t], base = g_tile_base[t], rows = g_tile_rows[t];
    int hbase = blockIdx.y * 128;

    __shared__ __align__(16) __half sAh[128 * LDA];
    __shared__ __align__(16) __half sAl[128 * LDA];
    __shared__ __align__(16) __half sBh[KB * LDB];
    __shared__ __align__(16) __half sBl[KB * LDB];

    int tid = threadIdx.x, wid = tid >> 5;
    int wm = wid & 3, wn = wid >> 2;

    const __half* w1h = g_w1hi + (size_t)e * DIM * HID;
    const __half* w1l = g_w1lo + (size_t)e * DIM * HID;

    wmma::fragment<wmma::accumulator, 16, 16, 16, float>  accM[2][4];
    wmma::fragment<wmma::accumulator, 16, 16, 16, __half> accR[2][4];
#pragma unroll
    for (int i = 0; i < 2; i++)
#pragma unroll
        for (int j = 0; j < 4; j++) {
            wmma::fill_fragment(accM[i][j], 0.f);
            wmma::fill_fragment(accR[i][j], __float2half(0.f));
        }

    int arow = tid >> 1, acol = (tid & 1) * 16;
    int tok = (arow < rows) ? g_ptok[base + arow] : -1;
    int brow = tid >> 3, bcol = (tid & 7) * 16;

    const int NC = DIM / KB;
    uint4 rAh0, rAh1, rAl0, rAl1, rB0, rB1, rB2, rB3;

    {
        rAh0 = rAh1 = rAl0 = rAl1 = make_uint4(0, 0, 0, 0);
        if (tok >= 0) {
            size_t s = (size_t)tok * DIM + acol;
            rAh0 = *(const uint4*)&g_xhi[s];
            rAh1 = *(const uint4*)&g_xhi[s + 8];
            rAl0 = *(const uint4*)&g_xlo[s];
            rAl1 = *(const uint4*)&g_xlo[s + 8];
        }
        size_t sB = (size_t)brow * HID + hbase + bcol;
        rB0 = *(const uint4*)&w1h[sB];
        rB1 = *(const uint4*)&w1h[sB + 8];
        rB2 = *(const uint4*)&w1l[sB];
        rB3 = *(const uint4*)&w1l[sB + 8];
    }

    for (int c = 0; c < NC; c++) {
        __syncthreads();
        *(uint4*)&sAh[arow * LDA + acol]     = rAh0;
        *(uint4*)&sAh[arow * LDA + acol + 8] = rAh1;
        *(uint4*)&sAl[arow * LDA + acol]     = rAl0;
        *(uint4*)&sAl[arow * LDA + acol + 8] = rAl1;
        *(uint4*)&sBh[brow * LDB + bcol]     = rB0;
        *(uint4*)&sBh[brow * LDB + bcol + 8] = rB1;
        *(uint4*)&sBl[brow * LDB + bcol]     = rB2;
        *(uint4*)&sBl[brow * LDB + bcol + 8] = rB3;
        __syncthreads();

        if (c + 1 < NC) {
            int k0 = (c + 1) * KB;
            rAh0 = rAh1 = rAl0 = rAl1 = make_uint4(0, 0, 0, 0);
            if (tok >= 0) {
                size_t s = (size_t)tok * DIM + k0 + acol;
                rAh0 = *(const uint4*)&g_xhi[s];
                rAh1 = *(const uint4*)&g_xhi[s + 8];
                rAl0 = *(const uint4*)&g_xlo[s];
                rAl1 = *(const uint4*)&g_xlo[s + 8];
            }
            size_t sB = (size_t)(k0 + brow) * HID + hbase + bcol;
            rB0 = *(const uint4*)&w1h[sB];
            rB1 = *(const uint4*)&w1h[sB + 8];
            rB2 = *(const uint4*)&w1l[sB];
            rB3 = *(const uint4*)&w1l[sB + 8];
        }

#pragma unroll
        for (int kk = 0; kk < KB / 16; kk++) {
            wmma::fragment<wmma::matrix_a, 16, 16, 16, __half, wmma::row_major> fah[2], fal[2];
#pragma unroll
            for (int i = 0; i < 2; i++) {
                wmma::load_matrix_sync(fah[i], &sAh[(wm * 32 + i * 16) * LDA + kk * 16], LDA);
                wmma::load_matrix_sync(fal[i], &sAl[(wm * 32 + i * 16) * LDA + kk * 16], LDA);
            }
#pragma unroll
            for (int j = 0; j < 4; j++) {
                wmma::fragment<wmma::matrix_b, 16, 16, 16, __half, wmma::row_major> fbh, fbl;
                wmma::load_matrix_sync(fbh, &sBh[kk * 16 * LDB + wn * 64 + j * 16], LDB);
                wmma::load_matrix_sync(fbl, &sBl[kk * 16 * LDB + wn * 64 + j * 16], LDB);
#pragma unroll
                for (int i = 0; i < 2; i++) {
                    wmma::mma_sync(accM[i][j], fah[i], fbh, accM[i][j]);  // f32 main
                    wmma::mma_sync(accR[i][j], fal[i], fbh, accR[i][j]);  // f16 residual
                    wmma::mma_sync(accR[i][j], fah[i], fbl, accR[i][j]);  // f16 residual
                }
            }
        }
    }

    // direct stores: tile exclusively owns its 128 rows (padded segments)
#pragma unroll
    for (int i = 0; i < 2; i++)
#pragma unroll
        for (int j = 0; j < 4; j++) {
            size_t ro = (size_t)(base - h0pos + wm * 32 + i * 16) * HID
                      + hbase + wn * 64 + j * 16;
            wmma::store_matrix_sync((float*)&g_h[ro], accM[i][j], HID,
                                    wmma::mem_row_major);
            wmma::store_matrix_sync(&g_hres[ro], accR[i][j], HID,
                                    wmma::mem_row_major);
        }
}

// ================= GELU + merge res + in-place pack (f16 hi|lo) ==============
__global__ void __launch_bounds__(256)
gelu_pack_kernel(const float* __restrict__ b1, int half_) {
    int h0, hend;
    half_rows(half_, h0, hend);
    int nquads = (hend - h0) * (HID / 4);
    int idx = blockIdx.x * blockDim.x + threadIdx.x;
    if (idx >= nquads) return;
    int rowo = idx / (HID / 4);
    int q = idx - rowo * (HID / 4);
    int pos = h0 + rowo;
    int e = 0;
#pragma unroll
    for (int k = 1; k < NEXP; k++) if (pos >= g_off[k]) e = k;
    const float* b1e = b1 + (size_t)e * HID + q * 4;
    size_t o = (size_t)rowo * HID + q * 4;
    float4 z4 = *(const float4*)&g_h[o];
    const __half2* rp = (const __half2*)&g_hres[o];
    __half2 r01 = rp[0], r23 = rp[1];
    float zz[4] = {z4.x + __low2float(r01), z4.y + __high2float(r01),
                   z4.z + __low2float(r23), z4.w + __high2float(r23)};
    unsigned int pk[4];
#pragma unroll
    for (int i = 0; i < 4; i++) {
        float z = zz[i] + b1e[i];
        float g = 0.5f * z * (1.0f + erff(z * 0.70710678118654752f));
        __half h = __float2half(g);
        __half l = __float2half(g - __half2float(h));
        pk[i] = (unsigned int)__half_as_ushort(h)
              | ((unsigned int)__half_as_ushort(l) << 16);
    }
    *(uint4*)&g_h[o] = *(uint4*)pk;
}

// ================= GEMM2: h @ w2[e] -> f32 main (g_y) + f16 res (g_yres) =====
__global__ void __launch_bounds__(256)
gemm2_mma(int half_) {
    int t, h0pos;
    if (!tile_range(half_, blockIdx.x, t, h0pos)) return;
    int e = g_tile_e[t], base = g_tile_base[t], rows = g_tile_rows[t];
    int dbase = blockIdx.y * 128;

    __shared__ __align__(16) __half sAh[128 * LDA];
    __shared__ __align__(16) __half sAl[128 * LDA];
    __shared__ __align__(16) __half sBh[KB * LDB];
    __shared__ __align__(16) __half sBl[KB * LDB];

    int tid = threadIdx.x, wid = tid >> 5;
    int wm = wid & 3, wn = wid >> 2;

    const __half* w2h = g_w2hi + (size_t)e * HID * DIM;
    const __half* w2l = g_w2lo + (size_t)e * HID * DIM;

    wmma::fragment<wmma::accumulator, 16, 16, 16, float>  accM[2][4];
    wmma::fragment<wmma::accumulator, 16, 16, 16, __half> accR[2][4];
#pragma unroll
    for (int i = 0; i < 2; i++)
#pragma unroll
        for (int j = 0; j < 4; j++) {
            wmma::fill_fragment(accM[i][j], 0.f);
            wmma::fill_fragment(accR[i][j], __float2half(0.f));
        }

    int arow = tid >> 1, acol = (tid & 1) * 16;
    bool okA = (arow < rows);
    size_t hrow = (size_t)(base - h0pos + arow) * HID;
    int brow = tid >> 3, bcol = (tid & 7) * 16;

    const int NC = HID / KB;
    uint4 p0, p1, p2, p3, rB0, rB1, rB2, rB3;

    {
        p0 = p1 = p2 = p3 = make_uint4(0, 0, 0, 0);
        if (okA) {
            p0 = *(const uint4*)&g_h[hrow + acol];
            p1 = *(const uint4*)&g_h[hrow + acol + 4];
            p2 = *(const uint4*)&g_h[hrow + acol + 8];
            p3 = *(const uint4*)&g_h[hrow + acol + 12];
        }
        size_t sB = (size_t)brow * DIM + dbase + bcol;
        rB0 = *(const uint4*)&w2h[sB];
        rB1 = *(const uint4*)&w2h[sB + 8];
        rB2 = *(const uint4*)&w2l[sB];
        rB3 = *(const uint4*)&w2l[sB + 8];
    }

    for (int c = 0; c < NC; c++) {
        __syncthreads();
        {
            unsigned int w[16] = {p0.x, p0.y, p0.z, p0.w, p1.x, p1.y, p1.z, p1.w,
                                  p2.x, p2.y, p2.z, p2.w, p3.x, p3.y, p3.z, p3.w};
            unsigned int hw[8], lw[8];
#pragma unroll
            for (int g = 0; g < 8; g++) {
                hw[g] = __byte_perm(w[2 * g], w[2 * g + 1], 0x5410);
                lw[g] = __byte_perm(w[2 * g], w[2 * g + 1], 0x7632);
            }
            *(uint4*)&sAh[arow * LDA + acol]     = *(uint4*)&hw[0];
            *(uint4*)&sAh[arow * LDA + acol + 8] = *(uint4*)&hw[4];
            *(uint4*)&sAl[arow * LDA + acol]     = *(uint4*)&lw[0];
            *(uint4*)&sAl[arow * LDA + acol + 8] = *(uint4*)&lw[4];
        }
        *(uint4*)&sBh[brow * LDB + bcol]     = rB0;
        *(uint4*)&sBh[brow * LDB + bcol + 8] = rB1;
        *(uint4*)&sBl[brow * LDB + bcol]     = rB2;
        *(uint4*)&sBl[brow * LDB + bcol + 8] = rB3;
        __syncthreads();

        if (c + 1 < NC) {
            int k0 = (c + 1) * KB;
            p0 = p1 = p2 = p3 = make_uint4(0, 0, 0, 0);
            if (okA) {
                p0 = *(const uint4*)&g_h[hrow + k0 + acol];
                p1 = *(const uint4*)&g_h[hrow + k0 + acol + 4];
                p2 = *(const uint4*)&g_h[hrow + k0 + acol + 8];
                p3 = *(const uint4*)&g_h[hrow + k0 + acol + 12];
            }
            size_t sB = (size_t)(k0 + brow) * DIM + dbase + bcol;
            rB0 = *(const uint4*)&w2h[sB];
            rB1 = *(const uint4*)&w2h[sB + 8];
            rB2 = *(const uint4*)&w2l[sB];
            rB3 = *(const uint4*)&w2l[sB + 8];
        }

#pragma unroll
        for (int kk = 0; kk < KB / 16; kk++) {
            wmma::fragment<wmma::matrix_a, 16, 16, 16, __half, wmma::row_major> fah[2], fal[2];
#pragma unroll
            for (int i = 0; i < 2; i++) {
                wmma::load_matrix_sync(fah[i], &sAh[(wm * 32 + i * 16) * LDA + kk * 16], LDA);
                wmma::load_matrix_sync(fal[i], &sAl[(wm * 32 + i * 16) * LDA + kk * 16], LDA);
            }
#pragma unroll
            for (int j = 0; j < 4; j++) {
                wmma::fragment<wmma::matrix_b, 16, 16, 16, __half, wmma::row_major> fbh, fbl;
                wmma::load_matrix_sync(fbh, &sBh[kk * 16 * LDB + wn * 64 + j * 16], LDB);
                wmma::load_matrix_sync(fbl, &sBl[kk * 16 * LDB + wn * 64 + j * 16], LDB);
#pragma unroll
                for (int i = 0; i < 2; i++) {
                    wmma::mma_sync(accM[i][j], fah[i], fbh, accM[i][j]);
                    wmma::mma_sync(accR[i][j], fal[i], fbh, accR[i][j]);
                    wmma::mma_sync(accR[i][j], fah[i], fbl, accR[i][j]);
                }
            }
        }
    }

#pragma unroll
    for (int i = 0; i < 2; i++)
#pragma unroll
        for (int j = 0; j < 4; j++) {
            size_t ro = (size_t)(base + wm * 32 + i * 16) * DIM
                      + dbase + wn * 64 + j * 16;
            wmma::store_matrix_sync(&g_y[ro], accM[i][j], DIM, wmma::mem_row_major);
            wmma::store_matrix_sync(&g_yres[ro], accR[i][j], DIM, wmma::mem_row_major);
        }
}

// ================= combine: main+res, bias + routing weight + sum ============
__global__ void combine_kernel(const float* __restrict__ b2,
                               float* __restrict__ out) {
    int idx = blockIdx.x * blockDim.x + threadIdx.x;
    if (idx >= N_TOK * (DIM / 4)) return;
    int n = idx >> 6, q = idx & 63;
    int p0 = g_tok2pos[2 * n + 0];
    int p1 = g_tok2pos[2 * n + 1];
    int e0 = g_topi[2 * n + 0];
    int e1 = g_topi[2 * n + 1];
    float w0 = g_topw[2 * n + 0];
    float w1 = g_topw[2 * n + 1];
    float4 y0 = ((const float4*)&g_y[(size_t)p0 * DIM])[q];
    float4 y1 = ((const float4*)&g_y[(size_t)p1 * DIM])[q];
    const __half2* r0p = (const __half2*)&g_yres[(size_t)p0 * DIM + q * 4];
    const __half2* r1p = (const __half2*)&g_yres[(size_t)p1 * DIM + q * 4];
    __half2 r0a = r0p[0], r0b = r0p[1], r1a = r1p[0], r1b = r1p[1];
    float4 c0 = ((const float4*)&b2[(size_t)e0 * DIM])[q];
    float4 c1 = ((const float4*)&b2[(size_t)e1 * DIM])[q];
    float4 r;
    r.x = w0 * (y0.x + __low2float(r0a)  + c0.x) + w1 * (y1.x + __low2float(r1a)  + c1.x);
    r.y = w0 * (y0.y + __high2float(r0a) + c0.y) + w1 * (y1.y + __high2float(r1a) + c1.y);
    r.z = w0 * (y0.z + __low2float(r0b)  + c0.z) + w1 * (y1.z + __low2float(r1b)  + c1.z);
    r.w = w0 * (y0.w + __high2float(r0b) + c0.w) + w1 * (y1.w + __high2float(r1b) + c1.w);
    ((float4*)out)[(size_t)n * 64 + q] = r;
}

// ================= launch =================
extern "C" void kernel_launch(void* const* d_in, const int* in_sizes, int n_in,
                              void* d_out, int out_size) {
    const float* x  = (const float*)d_in[0];
    const float* Wg = (const float*)d_in[1];
    const float* w1 = (const float*)d_in[2];
    const float* b1 = (const float*)d_in[3];
    const float* w2 = (const float*)d_in[4];
    const float* b2 = (const float*)d_in[5];
    float* out = (float*)d_out;

    init_kernel<<<1, 32>>>();
    gate_kernel<<<N_TOK / 4, 128>>>(x, Wg);
    prep_kernel<<<1, 1>>>();
    scatter_kernel<<<NASSIGN / 256, 256>>>();
    conv_x_kernel<<<(N_TOK * DIM / 8) / 256, 256>>>(x);
    conv_w1_kernel<<<(NEXP * DIM * HID / 8) / 256, 256>>>(w1);
    conv_w2_kernel<<<(NEXP * HID * DIM / 8) / 256, 256>>>(w2);
    int gelu_blocks = (HROWS * (HID / 4) + 255) / 256;
    for (int half_ = 0; half_ < 2; half_++) {
        gemm1_mma<<<dim3(HALF_TILES, HID / 128), 256>>>(half_);
        gelu_pack_kernel<<<gelu_blocks, 256>>>(b1, half_);
        gemm2_mma<<<dim3(HALF_TILES, DIM / 128), 256>>>(half_);
    }
    combine_kernel<<<(N_TOK * (DIM / 4)) / 256, 256>>>(b2, out);
}